// round 12
// baseline (speedup 1.0000x reference)
#include <cuda_runtime.h>

#define NN 50000
#define NE 1600000
#define HH 64
#define NG 16
#define DOUT 2

#define VPAD 68     // svec row stride (floats); 8 rows @ stride-8 hit banks {0,4..28}
#define NODES_B 128 // nodes per block

// Scratch (device globals; zero-initialized at load; consumers tail-zero)
__device__ __align__(16) float g_relu_sum[NN * HH];
__device__ float g_deg[NN];
__device__ __align__(16) float g_pooled[NG * HH];
__device__ int g_done;

// ---------------------------------------------------------------------------
// Edge scatter: warp processes 32 edges; coalesced RED.32 x2 per edge.
__global__ void __launch_bounds__(256) edge_kernel(
    const float* __restrict__ x,
    const int* __restrict__ ei,
    const float* __restrict__ ea,
    const float* __restrict__ ew1,   // [5,64]
    const float* __restrict__ eb1)   // [64]
{
    __shared__ __align__(16) float4 st4[8][32];
    __shared__ float stx[8][32];
    __shared__ int   stc[8][32];

    int warp = threadIdx.x >> 5, lane = threadIdx.x & 31;
    int e = (blockIdx.x * 8 + warp) * 32 + lane;   // NE % 256 == 0

    int ja = lane, jb = lane + 32;
    float w0a = __ldg(&ew1[0 * 64 + ja]), w1a = __ldg(&ew1[1 * 64 + ja]);
    float w2a = __ldg(&ew1[2 * 64 + ja]), w3a = __ldg(&ew1[3 * 64 + ja]);
    float w4a = __ldg(&ew1[4 * 64 + ja]), ba  = __ldg(&eb1[ja]);
    float w0b = __ldg(&ew1[0 * 64 + jb]), w1b = __ldg(&ew1[1 * 64 + jb]);
    float w2b = __ldg(&ew1[2 * 64 + jb]), w3b = __ldg(&ew1[3 * 64 + jb]);
    float w4b = __ldg(&ew1[4 * 64 + jb]), bb  = __ldg(&eb1[jb]);

    int r = __ldg(&ei[e]);
    int c = __ldg(&ei[NE + e]);
    float xr = __ldg(&x[r]);
    float xc = __ldg(&x[c]);
    float a0 = __ldg(&ea[3 * e + 0]);
    float a1 = __ldg(&ea[3 * e + 1]);
    float a2 = __ldg(&ea[3 * e + 2]);
    atomicAdd(&g_deg[c], 1.0f);

    st4[warp][lane] = make_float4(xr, a0, a1, a2);
    stx[warp][lane] = xc;
    stc[warp][lane] = c;
    __syncwarp();

#pragma unroll 8
    for (int k = 0; k < 32; k++) {
        float4 s  = st4[warp][k];
        float xck = stx[warp][k];
        int   ck  = stc[warp][k];
        float h0 = fmaf(s.x, w0a, fmaf(xck, w1a,
                   fmaf(s.y, w2a, fmaf(s.z, w3a, fmaf(s.w, w4a, ba)))));
        float h1 = fmaf(s.x, w0b, fmaf(xck, w1b,
                   fmaf(s.y, w2b, fmaf(s.z, w3b, fmaf(s.w, w4b, bb)))));
        float* dst = &g_relu_sum[(size_t)ck * HH];
        atomicAdd(dst + ja, fmaxf(h0, 0.f));
        atomicAdd(dst + jb, fmaxf(h1, 0.f));
    }
}

// ---------------------------------------------------------------------------
__device__ __forceinline__ void fma16(float4& a, float4 iv,
                                      float4 w0, float4 w1, float4 w2, float4 w3) {
    a.x = fmaf(iv.x, w0.x, a.x); a.y = fmaf(iv.x, w0.y, a.y);
    a.z = fmaf(iv.x, w0.z, a.z); a.w = fmaf(iv.x, w0.w, a.w);
    a.x = fmaf(iv.y, w1.x, a.x); a.y = fmaf(iv.y, w1.y, a.y);
    a.z = fmaf(iv.y, w1.z, a.z); a.w = fmaf(iv.y, w1.w, a.w);
    a.x = fmaf(iv.z, w2.x, a.x); a.y = fmaf(iv.z, w2.y, a.y);
    a.z = fmaf(iv.z, w2.z, a.z); a.w = fmaf(iv.z, w2.w, a.w);
    a.x = fmaf(iv.w, w3.x, a.x); a.y = fmaf(iv.w, w3.y, a.y);
    a.z = fmaf(iv.w, w3.z, a.z); a.w = fmaf(iv.w, w3.w, a.w);
}

// ---------------------------------------------------------------------------
// Fused node pipeline + head MLP (last block).
// 256 threads = 8 warps; warp covers 16 nodes (8 slots x M=2); 4 q-threads/node.
// Thread: M=2 nodes (stride 8), J=4 jv tiles (cols q*16..q*16+15).
// vs R11: half the per-thread work, double the grid (391 blocks -> ~21 warps/SM)
// and ~80 regs -> weight prefetch headroom. Crossbar ~32us, FFMA ~33us, overlap.
__global__ void __launch_bounds__(256, 3) node_out_kernel(
    const float* __restrict__ x,
    const int* __restrict__ batch,
    const float* __restrict__ ew2, const float* __restrict__ eb2,
    const float* __restrict__ nw1, const float* __restrict__ nb1,
    const float* __restrict__ nw2, const float* __restrict__ nb2,
    const float* __restrict__ ow1, const float* __restrict__ ob1,
    const float* __restrict__ ow2, const float* __restrict__ ob2,
    const float* __restrict__ ow3, const float* __restrict__ ob3,
    const float* __restrict__ ow4, const float* __restrict__ ob4,
    float* __restrict__ out)
{
    extern __shared__ __align__(16) float sm[];
    float* sw    = sm;                          // 4160 floats (65x64 max)
    float* svec  = sm + 4160;                   // NODES_B * VPAD = 8704
    float* sb    = sm + 4160 + NODES_B * VPAD;  // 64
    float* spool = sb + 64;                     // 1024

    int tid  = threadIdx.x;
    int warp = tid >> 5, lane = tid & 31;
    int n8 = lane >> 2, q = lane & 3;
    int base = blockIdx.x * NODES_B;
    int wrow = warp * 16 + n8;                  // local row for m=0

    int lrow[2], node[2];
    bool act[2];
#pragma unroll
    for (int m = 0; m < 2; m++) {
        lrow[m] = wrow + m * 8;
        node[m] = base + lrow[m];
        act[m]  = (node[m] < NN);
    }
    int nblk = min(NODES_B, NN - base);

    for (int i = tid; i < NG * HH; i += 256) spool[i] = 0.f;

    // Coalesced load + tail-zero of relu_sum
    float4* gin = (float4*)g_relu_sum + (size_t)base * 16;
    const float4 z4 = make_float4(0.f, 0.f, 0.f, 0.f);
    for (int i = tid; i < nblk * 16; i += 256) {
        int nn = i >> 4, kv = i & 15;
        *(float4*)&svec[nn * VPAD + kv * 4] = gin[i];
        gin[i] = z4;
    }
    for (int i = tid; i < 1024; i += 256) ((float4*)sw)[i] = ((const float4*)ew2)[i];
    if (tid < 64) sb[tid] = eb2[tid];
    __syncthreads();

    float dg[2], xn[2];
    int g[2];
#pragma unroll
    for (int m = 0; m < 2; m++) {
        dg[m] = 0.f; xn[m] = 0.f; g[m] = 0;
        if (act[m]) {
            dg[m] = g_deg[node[m]];
            if (q == 0) g_deg[node[m]] = 0.f;   // tail-zero once
            xn[m] = __ldg(&x[node[m]]);
            g[m]  = batch[node[m]];
        }
    }

    float4 acc[2][4];                           // [m][qq]
    int jc = q * 16;                            // output col base (floats)

    // ================= Phase A: agg = deg*eb2 + relu_sum @ ew2 =================
#pragma unroll
    for (int m = 0; m < 2; m++)
#pragma unroll
        for (int qq = 0; qq < 4; qq++) {
            const float* b4 = &sb[jc + qq * 4];
            acc[m][qq] = make_float4(dg[m]*b4[0], dg[m]*b4[1], dg[m]*b4[2], dg[m]*b4[3]);
        }
    for (int kv = 0; kv < 16; kv++) {
        float4 iv[2];
#pragma unroll
        for (int m = 0; m < 2; m++) iv[m] = *(const float4*)&svec[lrow[m]*VPAD + kv*4];
#pragma unroll
        for (int qq = 0; qq < 4; qq++) {
            const float* wr = &sw[kv * 4 * 64 + jc + qq * 4];
            float4 w0 = *(const float4*)(wr);
            float4 w1 = *(const float4*)(wr + 64);
            float4 w2 = *(const float4*)(wr + 128);
            float4 w3 = *(const float4*)(wr + 192);
#pragma unroll
            for (int m = 0; m < 2; m++) fma16(acc[m][qq], iv[m], w0, w1, w2, w3);
        }
    }
    __syncwarp();
#pragma unroll
    for (int m = 0; m < 2; m++)
        if (act[m])
#pragma unroll
            for (int qq = 0; qq < 4; qq++)
                *(float4*)&svec[lrow[m]*VPAD + jc + qq*4] = acc[m][qq];
    __syncthreads();

    for (int i = tid; i < 1040; i += 256) ((float4*)sw)[i] = ((const float4*)nw1)[i];
    if (tid < 64) sb[tid] = nb1[tid];
    __syncthreads();

    // ============ Phase B: t = relu(nb1 + x*nw1[0] + agg @ nw1[1:]) ============
#pragma unroll
    for (int m = 0; m < 2; m++)
#pragma unroll
        for (int qq = 0; qq < 4; qq++) {
            const float* b4 = &sb[jc + qq * 4];
            const float* w0r = &sw[jc + qq * 4];   // nw1 row 0
            acc[m][qq] = make_float4(fmaf(xn[m], w0r[0], b4[0]),
                                     fmaf(xn[m], w0r[1], b4[1]),
                                     fmaf(xn[m], w0r[2], b4[2]),
                                     fmaf(xn[m], w0r[3], b4[3]));
        }
    for (int kv = 0; kv < 16; kv++) {
        float4 iv[2];
#pragma unroll
        for (int m = 0; m < 2; m++) iv[m] = *(const float4*)&svec[lrow[m]*VPAD + kv*4];
#pragma unroll
        for (int qq = 0; qq < 4; qq++) {
            const float* wr = &sw[(kv * 4 + 1) * 64 + jc + qq * 4];
            float4 w0 = *(const float4*)(wr);
            float4 w1 = *(const float4*)(wr + 64);
            float4 w2 = *(const float4*)(wr + 128);
            float4 w3 = *(const float4*)(wr + 192);
#pragma unroll
            for (int m = 0; m < 2; m++) fma16(acc[m][qq], iv[m], w0, w1, w2, w3);
        }
    }
    __syncwarp();
#pragma unroll
    for (int m = 0; m < 2; m++)
        if (act[m])
#pragma unroll
            for (int qq = 0; qq < 4; qq++) {
                float4 a = acc[m][qq];
                a.x = fmaxf(a.x, 0.f); a.y = fmaxf(a.y, 0.f);
                a.z = fmaxf(a.z, 0.f); a.w = fmaxf(a.w, 0.f);
                *(float4*)&svec[lrow[m]*VPAD + jc + qq*4] = a;
            }
    __syncthreads();

    for (int i = tid; i < 1024; i += 256) ((float4*)sw)[i] = ((const float4*)nw2)[i];
    if (tid < 64) sb[tid] = nb2[tid];
    __syncthreads();

    // ================= Phase C: h = nb2 + t @ nw2; pool =================
#pragma unroll
    for (int m = 0; m < 2; m++)
#pragma unroll
        for (int qq = 0; qq < 4; qq++) {
            const float* b4 = &sb[jc + qq * 4];
            acc[m][qq] = make_float4(b4[0], b4[1], b4[2], b4[3]);
        }
    for (int kv = 0; kv < 16; kv++) {
        float4 iv[2];
#pragma unroll
        for (int m = 0; m < 2; m++) iv[m] = *(const float4*)&svec[lrow[m]*VPAD + kv*4];
#pragma unroll
        for (int qq = 0; qq < 4; qq++) {
            const float* wr = &sw[kv * 4 * 64 + jc + qq * 4];
            float4 w0 = *(const float4*)(wr);
            float4 w1 = *(const float4*)(wr + 64);
            float4 w2 = *(const float4*)(wr + 128);
            float4 w3 = *(const float4*)(wr + 192);
#pragma unroll
            for (int m = 0; m < 2; m++) fma16(acc[m][qq], iv[m], w0, w1, w2, w3);
        }
    }
#pragma unroll
    for (int m = 0; m < 2; m++)
        if (act[m])
#pragma unroll
            for (int qq = 0; qq < 4; qq++) {
                float* dst = &spool[g[m] * HH + jc + qq * 4];
                atomicAdd(dst + 0, acc[m][qq].x);
                atomicAdd(dst + 1, acc[m][qq].y);
                atomicAdd(dst + 2, acc[m][qq].z);
                atomicAdd(dst + 3, acc[m][qq].w);
            }
    __syncthreads();
    for (int i = tid; i < NG * HH; i += 256)
        atomicAdd(&g_pooled[i], spool[i]);

    // ---- last-block: head MLP ----
    __shared__ int s_last;
    __syncthreads();
    if (tid == 0) {
        __threadfence();
        int done = atomicAdd(&g_done, 1);
        s_last = (done == (int)gridDim.x - 1) ? 1 : 0;
    }
    __syncthreads();
    if (!s_last) return;
    __threadfence();

    float* sa   = spool;
    float* sbuf = svec;                     // 8704 floats, plenty
    for (int i = tid; i < NG * HH; i += 256) {
        sa[i] = __ldcg(&g_pooled[i]);
        g_pooled[i] = 0.f;
    }
    if (tid == 0) g_done = 0;
    __syncthreads();

#pragma unroll
    for (int it = 0; it < 4; it++) {
        int item = tid + it * 256;
        int gg = item >> 6, j = item & 63;
        float v = __ldg(&ob1[j]);
#pragma unroll 16
        for (int k = 0; k < 64; k++) v = fmaf(sa[gg * 64 + k], __ldg(&ow1[k * 64 + j]), v);
        sbuf[item] = fmaxf(v, 0.f);
    }
    __syncthreads();
#pragma unroll
    for (int it = 0; it < 4; it++) {
        int item = tid + it * 256;
        int gg = item >> 6, j = item & 63;
        float v = __ldg(&ob2[j]);
#pragma unroll 16
        for (int k = 0; k < 64; k++) v = fmaf(sbuf[gg * 64 + k], __ldg(&ow2[k * 64 + j]), v);
        sa[item] = fmaxf(v, 0.f);
    }
    __syncthreads();
#pragma unroll
    for (int it = 0; it < 4; it++) {
        int item = tid + it * 256;
        int gg = item >> 6, j = item & 63;
        float v = __ldg(&ob3[j]);
#pragma unroll 16
        for (int k = 0; k < 64; k++) v = fmaf(sa[gg * 64 + k], __ldg(&ow3[k * 64 + j]), v);
        sbuf[item] = fmaxf(v, 0.f);
    }
    __syncthreads();
    if (tid < NG * DOUT) {
        int gg = tid / DOUT, j = tid % DOUT;
        float o = __ldg(&ob4[j]);
#pragma unroll 16
        for (int k = 0; k < 64; k++)
            o = fmaf(sbuf[gg * 64 + k], __ldg(&ow4[k * DOUT + j]), o);
        out[gg * DOUT + j] = o;
    }
}

// ---------------------------------------------------------------------------
extern "C" void kernel_launch(void* const* d_in, const int* in_sizes, int n_in,
                              void* d_out, int out_size) {
    const float* x     = (const float*)d_in[0];
    const int* ei      = (const int*)d_in[1];
    const float* ea    = (const float*)d_in[2];
    const int* batch   = (const int*)d_in[3];
    const float* ew1 = (const float*)d_in[4];
    const float* eb1 = (const float*)d_in[5];
    const float* ew2 = (const float*)d_in[6];
    const float* eb2 = (const float*)d_in[7];
    const float* nw1 = (const float*)d_in[8];
    const float* nb1 = (const float*)d_in[9];
    const float* nw2 = (const float*)d_in[10];
    const float* nb2 = (const float*)d_in[11];
    const float* ow1 = (const float*)d_in[12];
    const float* ob1 = (const float*)d_in[13];
    const float* ow2 = (const float*)d_in[14];
    const float* ob2 = (const float*)d_in[15];
    const float* ow3 = (const float*)d_in[16];
    const float* ob3 = (const float*)d_in[17];
    const float* ow4 = (const float*)d_in[18];
    const float* ob4 = (const float*)d_in[19];
    float* out = (float*)d_out;

    const int node_smem = (4160 + NODES_B * VPAD + 64 + 1024) * 4;   // 55808 B
    static int smem_set = 0;
    if (!smem_set) {
        cudaFuncSetAttribute(node_out_kernel,
                             cudaFuncAttributeMaxDynamicSharedMemorySize, node_smem);
        smem_set = 1;
    }

    edge_kernel<<<NE / 256, 256>>>(x, ei, ea, ew1, eb1);               // 1
    node_out_kernel<<<(NN + NODES_B - 1) / NODES_B, 256, node_smem>>>( // 2
        x, batch, ew2, eb2, nw1, nb1, nw2, nb2,
        ow1, ob1, ow2, ob2, ow3, ob3, ow4, ob4, out);
}

// round 13
// speedup vs baseline: 1.4056x; 1.4056x over previous
#include <cuda_runtime.h>

#define NN 50000
#define NE 1600000
#define HH 64
#define NG 16
#define DOUT 2

#define VPAD 68
#define NODES_B 128

// Scratch (device globals; zero-initialized at load; consumers tail-zero)
__device__ __align__(16) float g_relu_sum[NN * HH];
__device__ float g_deg[NN];
__device__ __align__(16) float g_pooled[NG * HH];
__device__ int g_done;

// ---------------------------------------------------------------------------
// Edge scatter: warp processes 32 edges; coalesced RED.32 x2 per edge.
__global__ void __launch_bounds__(256) edge_kernel(
    const float* __restrict__ x,
    const int* __restrict__ ei,
    const float* __restrict__ ea,
    const float* __restrict__ ew1,   // [5,64]
    const float* __restrict__ eb1)   // [64]
{
    __shared__ __align__(16) float4 st4[8][32];
    __shared__ float stx[8][32];
    __shared__ int   stc[8][32];

    int warp = threadIdx.x >> 5, lane = threadIdx.x & 31;
    int e = (blockIdx.x * 8 + warp) * 32 + lane;   // NE % 256 == 0

    int ja = lane, jb = lane + 32;
    float w0a = __ldg(&ew1[0 * 64 + ja]), w1a = __ldg(&ew1[1 * 64 + ja]);
    float w2a = __ldg(&ew1[2 * 64 + ja]), w3a = __ldg(&ew1[3 * 64 + ja]);
    float w4a = __ldg(&ew1[4 * 64 + ja]), ba  = __ldg(&eb1[ja]);
    float w0b = __ldg(&ew1[0 * 64 + jb]), w1b = __ldg(&ew1[1 * 64 + jb]);
    float w2b = __ldg(&ew1[2 * 64 + jb]), w3b = __ldg(&ew1[3 * 64 + jb]);
    float w4b = __ldg(&ew1[4 * 64 + jb]), bb  = __ldg(&eb1[jb]);

    int r = __ldg(&ei[e]);
    int c = __ldg(&ei[NE + e]);
    float xr = __ldg(&x[r]);
    float xc = __ldg(&x[c]);
    float a0 = __ldg(&ea[3 * e + 0]);
    float a1 = __ldg(&ea[3 * e + 1]);
    float a2 = __ldg(&ea[3 * e + 2]);
    atomicAdd(&g_deg[c], 1.0f);

    st4[warp][lane] = make_float4(xr, a0, a1, a2);
    stx[warp][lane] = xc;
    stc[warp][lane] = c;
    __syncwarp();

#pragma unroll 8
    for (int k = 0; k < 32; k++) {
        float4 s  = st4[warp][k];
        float xck = stx[warp][k];
        int   ck  = stc[warp][k];
        float h0 = fmaf(s.x, w0a, fmaf(xck, w1a,
                   fmaf(s.y, w2a, fmaf(s.z, w3a, fmaf(s.w, w4a, ba)))));
        float h1 = fmaf(s.x, w0b, fmaf(xck, w1b,
                   fmaf(s.y, w2b, fmaf(s.z, w3b, fmaf(s.w, w4b, bb)))));
        float* dst = &g_relu_sum[(size_t)ck * HH];
        atomicAdd(dst + ja, fmaxf(h0, 0.f));
        atomicAdd(dst + jb, fmaxf(h1, 0.f));
    }
}

// ---------------------------------------------------------------------------
// Column-parallel GEMV core: thread owns output col j (weights in REGISTERS),
// streams nodes; iv comes from broadcast LDS.128 (independent, pipelineable).
__device__ __forceinline__ float dot64(const float* __restrict__ row,
                                       const float* __restrict__ w, float acc) {
#pragma unroll
    for (int kq = 0; kq < 16; kq++) {
        float4 v = *(const float4*)&row[kq * 4];   // broadcast LDS.128
        acc = fmaf(v.x, w[kq * 4 + 0], acc);
        acc = fmaf(v.y, w[kq * 4 + 1], acc);
        acc = fmaf(v.z, w[kq * 4 + 2], acc);
        acc = fmaf(v.w, w[kq * 4 + 3], acc);
    }
    return acc;
}

// ---------------------------------------------------------------------------
// Fused node pipeline + head MLP (last block).
// 256 threads: j = tid&63 (output column), mslot = tid>>6 (node subset, stride 4).
// Weights held in regs (64/thread, reloaded per phase via L1-hot LDG).
// Ping-pong svecA/svecB between phases.
__global__ void __launch_bounds__(256, 3) node_out_kernel(
    const float* __restrict__ x,
    const int* __restrict__ batch,
    const float* __restrict__ ew2, const float* __restrict__ eb2,
    const float* __restrict__ nw1, const float* __restrict__ nb1,
    const float* __restrict__ nw2, const float* __restrict__ nb2,
    const float* __restrict__ ow1, const float* __restrict__ ob1,
    const float* __restrict__ ow2, const float* __restrict__ ob2,
    const float* __restrict__ ow3, const float* __restrict__ ob3,
    const float* __restrict__ ow4, const float* __restrict__ ob4,
    float* __restrict__ out)
{
    extern __shared__ __align__(16) float sm[];
    float* svecA = sm;                               // NODES_B*VPAD = 8704
    float* svecB = sm + NODES_B * VPAD;              // 8704
    float* sdg   = sm + 2 * NODES_B * VPAD;          // 128
    float* sxn   = sdg + NODES_B;                    // 128
    int*   sgb   = (int*)(sxn + NODES_B);            // 128
    float* spool = sxn + 2 * NODES_B;                // 1024

    int tid = threadIdx.x;
    int base = blockIdx.x * NODES_B;
    int nblk = min(NODES_B, NN - base);

    for (int i = tid; i < NG * HH; i += 256) spool[i] = 0.f;

    // Stage relu_sum rows (coalesced) + tail-zero; stage per-node scalars.
    float4* gin = (float4*)g_relu_sum + (size_t)base * 16;
    const float4 z4 = make_float4(0.f, 0.f, 0.f, 0.f);
    for (int i = tid; i < nblk * 16; i += 256) {
        int nn = i >> 4, kv = i & 15;
        *(float4*)&svecA[nn * VPAD + kv * 4] = gin[i];
        gin[i] = z4;
    }
    if (tid < nblk) {
        int n = base + tid;
        sdg[tid] = g_deg[n];
        g_deg[n] = 0.f;                              // tail-zero
        sxn[tid] = __ldg(&x[n]);
        sgb[tid] = batch[n];
    }
    __syncthreads();

    int j = tid & 63;
    int mslot = tid >> 6;                            // 0..3

    float w[64];

    // ================= Phase A: B = deg*eb2 + A @ ew2 =================
    {
        float bj = __ldg(&eb2[j]);
#pragma unroll
        for (int k = 0; k < 64; k++) w[k] = __ldg(&ew2[k * 64 + j]);
#pragma unroll 2
        for (int i = 0; i < NODES_B / 4; i++) {
            int n = mslot + i * 4;
            if (n < nblk) {
                float acc = dot64(&svecA[n * VPAD], w, sdg[n] * bj);
                svecB[n * VPAD + j] = acc;           // lanes j0-31 consecutive: no conflict
            }
        }
    }
    __syncthreads();

    // ============ Phase B: A = relu(nb1 + x*nw1[0] + B @ nw1[1:]) ============
    {
        float bj  = __ldg(&nb1[j]);
        float w0j = __ldg(&nw1[j]);                  // row 0 (x term)
#pragma unroll
        for (int k = 0; k < 64; k++) w[k] = __ldg(&nw1[(k + 1) * 64 + j]);
#pragma unroll 2
        for (int i = 0; i < NODES_B / 4; i++) {
            int n = mslot + i * 4;
            if (n < nblk) {
                float acc = dot64(&svecB[n * VPAD], w, fmaf(sxn[n], w0j, bj));
                svecA[n * VPAD + j] = fmaxf(acc, 0.f);
            }
        }
    }
    __syncthreads();

    // ================= Phase C: h = nb2 + A @ nw2; pool =================
    {
        float bj = __ldg(&nb2[j]);
#pragma unroll
        for (int k = 0; k < 64; k++) w[k] = __ldg(&nw2[k * 64 + j]);
#pragma unroll 2
        for (int i = 0; i < NODES_B / 4; i++) {
            int n = mslot + i * 4;
            if (n < nblk) {
                float acc = dot64(&svecA[n * VPAD], w, bj);
                atomicAdd(&spool[sgb[n] * HH + j], acc);   // consecutive j: no conflict
            }
        }
    }
    __syncthreads();
    for (int i = tid; i < NG * HH; i += 256)
        atomicAdd(&g_pooled[i], spool[i]);

    // ---- last-block: head MLP ----
    __shared__ int s_last;
    __syncthreads();
    if (tid == 0) {
        __threadfence();
        int done = atomicAdd(&g_done, 1);
        s_last = (done == (int)gridDim.x - 1) ? 1 : 0;
    }
    __syncthreads();
    if (!s_last) return;
    __threadfence();

    float* sa   = spool;
    float* sbuf = svecA;                             // 8704 floats, plenty
    for (int i = tid; i < NG * HH; i += 256) {
        sa[i] = __ldcg(&g_pooled[i]);
        g_pooled[i] = 0.f;
    }
    if (tid == 0) g_done = 0;
    __syncthreads();

#pragma unroll
    for (int it = 0; it < 4; it++) {
        int item = tid + it * 256;
        int gg = item >> 6, jj = item & 63;
        float v = __ldg(&ob1[jj]);
#pragma unroll 16
        for (int k = 0; k < 64; k++) v = fmaf(sa[gg * 64 + k], __ldg(&ow1[k * 64 + jj]), v);
        sbuf[item] = fmaxf(v, 0.f);
    }
    __syncthreads();
#pragma unroll
    for (int it = 0; it < 4; it++) {
        int item = tid + it * 256;
        int gg = item >> 6, jj = item & 63;
        float v = __ldg(&ob2[jj]);
#pragma unroll 16
        for (int k = 0; k < 64; k++) v = fmaf(sbuf[gg * 64 + k], __ldg(&ow2[k * 64 + jj]), v);
        sa[item] = fmaxf(v, 0.f);
    }
    __syncthreads();
#pragma unroll
    for (int it = 0; it < 4; it++) {
        int item = tid + it * 256;
        int gg = item >> 6, jj = item & 63;
        float v = __ldg(&ob3[jj]);
#pragma unroll 16
        for (int k = 0; k < 64; k++) v = fmaf(sa[gg * 64 + k], __ldg(&ow3[k * 64 + jj]), v);
        sbuf[item] = fmaxf(v, 0.f);
    }
    __syncthreads();
    if (tid < NG * DOUT) {
        int gg = tid / DOUT, jj = tid % DOUT;
        float o = __ldg(&ob4[jj]);
#pragma unroll 16
        for (int k = 0; k < 64; k++)
            o = fmaf(sbuf[gg * 64 + k], __ldg(&ow4[k * DOUT + jj]), o);
        out[gg * DOUT + jj] = o;
    }
}

// ---------------------------------------------------------------------------
extern "C" void kernel_launch(void* const* d_in, const int* in_sizes, int n_in,
                              void* d_out, int out_size) {
    const float* x     = (const float*)d_in[0];
    const int* ei      = (const int*)d_in[1];
    const float* ea    = (const float*)d_in[2];
    const int* batch   = (const int*)d_in[3];
    const float* ew1 = (const float*)d_in[4];
    const float* eb1 = (const float*)d_in[5];
    const float* ew2 = (const float*)d_in[6];
    const float* eb2 = (const float*)d_in[7];
    const float* nw1 = (const float*)d_in[8];
    const float* nb1 = (const float*)d_in[9];
    const float* nw2 = (const float*)d_in[10];
    const float* nb2 = (const float*)d_in[11];
    const float* ow1 = (const float*)d_in[12];
    const float* ob1 = (const float*)d_in[13];
    const float* ow2 = (const float*)d_in[14];
    const float* ob2 = (const float*)d_in[15];
    const float* ow3 = (const float*)d_in[16];
    const float* ob3 = (const float*)d_in[17];
    const float* ow4 = (const float*)d_in[18];
    const float* ob4 = (const float*)d_in[19];
    float* out = (float*)d_out;

    // svecA + svecB + sdg + sxn + sgb + spool
    const int node_smem = (2 * NODES_B * VPAD + 3 * NODES_B + NG * HH) * 4;  // 75264 B
    static int smem_set = 0;
    if (!smem_set) {
        cudaFuncSetAttribute(node_out_kernel,
                             cudaFuncAttributeMaxDynamicSharedMemorySize, node_smem);
        smem_set = 1;
    }

    edge_kernel<<<NE / 256, 256>>>(x, ei, ea, ew1, eb1);               // 1
    node_out_kernel<<<(NN + NODES_B - 1) / NODES_B, 256, node_smem>>>( // 2
        x, batch, ew2, eb2, nw1, nb1, nw2, nb2,
        ow1, ob1, ow2, ob2, ow3, ob3, ow4, ob4, out);
}